// round 16
// baseline (speedup 1.0000x reference)
#include <cuda_runtime.h>
#include <cuda_fp16.h>
#include <cstdint>
#include <cstddef>

#define BB 64
#define TT 31
#define SS 32
#define VV 34004
#define EE 300
#define HH 512
#define MD 1024
#define BH (BB*HH)
#define Z4H 2048
#define NBLK 128
#define NPAD 34048            // 266 * 128
#define MPAD 2048
#define NXB 266
#define NTILES (16*NXB)       // 4256
#define GRID_FUSED 296
#define NWORK (GRID_FUSED - NBLK)   // 168

// prologue queue 1 (loop prereqs)
#define NT_INIT 16
#define NT_TW2  1024
#define NT_TWQ  256
#define NT_ZX   992
#define NT_KEY  256
#define NT_P    256
#define PB_INIT 0
#define PB_TW2  (PB_INIT + NT_INIT)      // 16
#define PB_TWQ  (PB_TW2 + NT_TW2)        // 1040
#define PB_ZX   (PB_TWQ + NT_TWQ)        // 1296
#define PB_KEY  (PB_ZX + NT_ZX)          // 2288
#define PB_P    (PB_KEY + NT_KEY)        // 2544
#define P1TOTAL (PB_P + NT_P)            // 2800
// queue 2 (cvtB, mma-only dependency)
#define NT_CVTB 4256

typedef unsigned long long ull;

// ----------------------------- device scratch --------------------------------
__device__ __align__(16) float g_keys[BB*SS*HH];
__device__ __align__(16) float g_P[BB*SS*HH];
__device__ __align__(16) float g_zx[BB*TT*Z4H];        // [t][n][m] transposed
__device__ __align__(16) ull   g_W2I[1024*1024];       // [gp*512+h][k] pairs
__device__ __align__(16) ull   g_WQAI[512*512];        // [n][k] (Wq,Wa) pairs
__device__ __align__(16) float g_h[2][BH];             // [m][h]
__device__ __align__(16) float g_cT[HH*BB];            // [h][m]
__device__ __align__(16) float g_aprev[BH];            // [m][n]
__device__ __align__(16) float g_q[BH];
__device__ __align__(16) float g_e[BH];
__device__ __align__(16) __half g_Ah[MPAD*HH];         // rows t*64+b (fp16)
__device__ __align__(16) __half g_Bh[(size_t)NPAD*HH]; // fp16
__device__ __align__(128) unsigned g_cnt8[8*32];       // tree sub-counters (1/line)
__device__ unsigned g_cntm;                             // master counter
__device__ unsigned g_gen;
__device__ unsigned g_gen2;
__device__ unsigned g_tile;
__device__ unsigned g_ptile;
__device__ unsigned g_ptile2;
__device__ unsigned g_pdone;
__device__ unsigned g_cdone;

// ----------------------------- scalar helpers --------------------------------
__device__ __forceinline__ ull pack2(float x, float y) {
    ull r; asm("mov.b64 %0, {%1,%2};" : "=l"(r) : "f"(x), "f"(y)); return r;
}
__device__ __forceinline__ ull fma2(ull a, ull b, ull c) {
    ull d; asm("fma.rn.f32x2 %0, %1, %2, %3;" : "=l"(d) : "l"(a), "l"(b), "l"(c)); return d;
}
__device__ __forceinline__ float2 unpack2(ull a) {
    float2 f; asm("mov.b64 {%0,%1}, %2;" : "=f"(f.x), "=f"(f.y) : "l"(a)); return f;
}
__device__ __forceinline__ float tanh_a(float x) {
    float y; asm("tanh.approx.f32 %0, %1;" : "=f"(y) : "f"(x)); return y;
}
__device__ __forceinline__ uint32_t smem_u32(const void* p) {
    uint32_t a;
    asm("{ .reg .u64 t; cvta.to.shared.u64 t, %1; cvt.u32.u64 %0, t; }" : "=r"(a) : "l"(p));
    return a;
}
__device__ __forceinline__ unsigned ld_acq(const unsigned* p) {
    unsigned v; asm volatile("ld.acquire.gpu.global.u32 %0, [%1];" : "=r"(v) : "l"(p) : "memory"); return v;
}
__device__ __forceinline__ unsigned ld_rlx(const unsigned* p) {
    unsigned v; asm volatile("ld.relaxed.gpu.global.u32 %0, [%1];" : "=r"(v) : "l"(p) : "memory"); return v;
}
__device__ __forceinline__ void st_rel(unsigned* p, unsigned v) {
    asm volatile("st.release.gpu.global.u32 [%0], %1;" :: "l"(p), "r"(v) : "memory");
}
__device__ __forceinline__ void st_rlx(unsigned* p, unsigned v) {
    asm volatile("st.relaxed.gpu.global.u32 [%0], %1;" :: "l"(p), "r"(v) : "memory");
}
__device__ __forceinline__ unsigned atom_add_ar(unsigned* p, unsigned v) {
    unsigned o; asm volatile("atom.acq_rel.gpu.global.add.u32 %0, [%1], %2;"
                             : "=r"(o) : "l"(p), "r"(v) : "memory"); return o;
}

// tree barrier: 8 sub-counters -> master -> g_gen = want
__device__ __forceinline__ void gbar2(unsigned want, int sub, unsigned subtot, bool arrive) {
    __syncthreads();
    if (threadIdx.x == 0) {
        if (arrive) {
            unsigned a = atom_add_ar(&g_cnt8[sub*32], 1u);
            if (a == subtot - 1u) {
                st_rlx(&g_cnt8[sub*32], 0u);
                unsigned b = atom_add_ar(&g_cntm, 1u);
                if (b == 7u) {
                    st_rlx(&g_cntm, 0u);
                    st_rel(&g_gen, want);
                    st_rel(&g_gen2, want);
                }
            }
        }
        while (ld_rlx(&g_gen) < want) { }
        (void)ld_acq(&g_gen);
    }
    __syncthreads();
}

// ----------------------------- reset (per graph replay) ------------------------
__global__ void k_rst() {
    int tid = threadIdx.x;
    if (tid < 8) g_cnt8[tid*32] = 0u;
    if (tid == 0) {
        g_cntm = 0; g_gen = 0; g_gen2 = 0; g_tile = 0;
        g_ptile = 0; g_ptile2 = 0; g_pdone = 0; g_cdone = 0;
    }
}

// ----------------------------- async primitives --------------------------------
__device__ __forceinline__ void cpasync16(uint32_t saddr, const void* g) {
    asm volatile("cp.async.cg.shared.global [%0], [%1], 16;" :: "r"(saddr), "l"(g));
}
__device__ __forceinline__ void cp_commit() { asm volatile("cp.async.commit_group;"); }
__device__ __forceinline__ void cp_wait1()  { asm volatile("cp.async.wait_group 1;"); }
__device__ __forceinline__ void cp_wait0()  { asm volatile("cp.async.wait_group 0;"); }

// ----------------------------- mma primitives ---------------------------------
#define ROWB 80
#define TILEB (128*ROWB)        // 10240
#define STAGEB (2*TILEB)        // 20480 (Ah, Bh)
#define SMEM_FUSED 61440

__device__ __forceinline__ void ldsm4(uint32_t* r, uint32_t addr) {
    asm volatile("ldmatrix.sync.aligned.m8n8.x4.shared.b16 {%0,%1,%2,%3}, [%4];"
                 : "=r"(r[0]), "=r"(r[1]), "=r"(r[2]), "=r"(r[3]) : "r"(addr));
}
__device__ __forceinline__ void ldsm2(uint32_t* r, uint32_t addr) {
    asm volatile("ldmatrix.sync.aligned.m8n8.x2.shared.b16 {%0,%1}, [%2];"
                 : "=r"(r[0]), "=r"(r[1]) : "r"(addr));
}
__device__ __forceinline__ void mma16816(float* c, const uint32_t* a, const uint32_t* b) {
    asm volatile("mma.sync.aligned.m16n8k16.row.col.f32.f16.f16.f32 "
                 "{%0,%1,%2,%3}, {%4,%5,%6,%7}, {%8,%9}, {%0,%1,%2,%3};"
                 : "+f"(c[0]), "+f"(c[1]), "+f"(c[2]), "+f"(c[3])
                 : "r"(a[0]), "r"(a[1]), "r"(a[2]), "r"(a[3]), "r"(b[0]), "r"(b[1]));
}

// ----------------------------- prologue tile bodies ---------------------------
struct PSmem {                 // transpose tiles
    float t0[32][33];
    float t1[32][33];
};
struct GSmem {                 // fp32 GEMM tiles
    float As[16][65];
    float Bsh[16][64];
    float Ts[64][65];          // zx only
};

__device__ void p_init(int i, int tid, const float* h0, const float* c0) {
#pragma unroll
    for (int u = 0; u < 8; u++) {
        int idx = i*2048 + u*256 + tid;
        int b = idx >> 9, h = idx & 511;
        g_h[0][idx] = h0[idx];
        g_cT[h*BB + b] = c0[idx];
        g_aprev[idx] = 0.f;
        size_t o = (size_t)(BB*TT)*HH + idx;
        g_Ah[o] = __float2half(0.f);
    }
}

__device__ void p_tw2(PSmem* ps, int r, int tid,
                      const float* __restrict__ Wk, const float* __restrict__ Wr) {
    int gp = r >> 9, r2 = r & 511;
    int h0 = (r2 >> 5) * 32, k0 = (r2 & 31) * 32;
    int tx = tid & 31, ty = tid >> 5;
#pragma unroll
    for (int ii = 0; ii < 4; ii++) {
        int kk = ty + 8*ii;
        int kg = k0 + kk;
        int n0 = gp*1024 + h0 + tx;
        float a, b;
        if (kg < 512) {
            a = Wk[(size_t)(300 + kg)*Z4H + n0];
            b = Wk[(size_t)(300 + kg)*Z4H + n0 + 512];
        } else {
            a = Wr[(size_t)(kg - 512)*Z4H + n0];
            b = Wr[(size_t)(kg - 512)*Z4H + n0 + 512];
        }
        ps->t0[kk][tx] = a; ps->t1[kk][tx] = b;
    }
    __syncthreads();
#pragma unroll
    for (int ii = 0; ii < 4; ii++) {
        int nl = ty + 8*ii;
        g_W2I[(size_t)(gp*512 + h0 + nl)*1024 + k0 + tx] = pack2(ps->t0[tx][nl], ps->t1[tx][nl]);
    }
}

__device__ void p_twq(PSmem* ps, int r, int tid,
                      const float* __restrict__ Wq, const float* __restrict__ Wa) {
    int k0 = (r & 15) * 32, n0 = (r >> 4) * 32;
    int tx = tid & 31, ty = tid >> 5;
#pragma unroll
    for (int ii = 0; ii < 4; ii++) {
        int kk = ty + 8*ii;
        ps->t0[kk][tx] = Wq[(size_t)(k0 + kk)*HH + n0 + tx];
        ps->t1[kk][tx] = Wa[(size_t)(k0 + kk)*HH + n0 + tx];
    }
    __syncthreads();
#pragma unroll
    for (int ii = 0; ii < 4; ii++) {
        int nl = ty + 8*ii;
        g_WQAI[(size_t)(n0 + nl)*HH + k0 + tx] = pack2(ps->t0[tx][nl], ps->t1[tx][nl]);
    }
}

__device__ void p_cvtB(PSmem* ps, int r, int tid, const float* __restrict__ Wfc) {
    int ng = r >> 2, kg = r & 3;
    int n0 = ng * 32;
    int tx = tid & 31, ty = tid >> 5;
#pragma unroll
    for (int sub = 0; sub < 4; sub++) {
        int k0 = kg*128 + sub*32;
#pragma unroll
        for (int ii = 0; ii < 4; ii++) {
            int kk = ty + 8*ii;
            int n = n0 + tx;
            ps->t0[kk][tx] = (n < VV) ? Wfc[(size_t)(k0 + kk)*VV + n] : 0.f;
        }
        __syncthreads();
#pragma unroll
        for (int ii = 0; ii < 4; ii++) {
            int nl = ty + 8*ii;
            float v = ps->t0[tx][nl];
            size_t o = (size_t)(n0 + nl)*HH + k0 + tx;
            g_Bh[o] = __float2half(v);
        }
        __syncthreads();
    }
}

// zx tile: out[t][bn..bn+64)[m] = (emb[tok] @ Wk[0:300]) + bias, transposed store
__device__ void p_zx(GSmem* gs, int r, int tid,
                     const void* __restrict__ dec, const float* __restrict__ emb,
                     const float* __restrict__ Wk, const float* __restrict__ bb) {
    int t = r >> 5, bn = (r & 31) * 64;
    const long long* p64 = (const long long*)dec;
    bool is64 = true;
#pragma unroll
    for (int i = 0; i < 4; i++) { long long v = p64[i]; if (v < 0 || v >= VV) is64 = false; }

    int tm = (tid >> 4) * 4, tn = (tid & 15) * 4;
    int m = tid >> 2, ks4 = (tid & 3) * 4;
    long long tok = is64 ? p64[m*TT + t] : (long long)((const int*)dec)[m*TT + t];
    const float* arow = emb + (size_t)tok * EE;

    ull acc[4][2];
#pragma unroll
    for (int i = 0; i < 4; i++) { acc[i][0] = 0ull; acc[i][1] = 0ull; }
    for (int kb = 0; kb < EE; kb += 16) {
        float4 a4 = make_float4(0.f, 0.f, 0.f, 0.f);
        if (kb + ks4 < EE) a4 = *(const float4*)(arow + kb + ks4);
        gs->As[ks4+0][m] = a4.x; gs->As[ks4+1][m] = a4.y;
        gs->As[ks4+2][m] = a4.z; gs->As[ks4+3][m] = a4.w;
        int kl = tid >> 4, c = (tid & 15) * 4;
        float4 b4 = make_float4(0.f, 0.f, 0.f, 0.f);
        if (kb + kl < EE) b4 = *(const float4*)(Wk + (size_t)(kb + kl)*Z4H + bn + c);
        *(float4*)&gs->Bsh[kl][c] = b4;
        __syncthreads();
#pragma unroll
        for (int k = 0; k < 16; k++) {
            float4 bq = *(const float4*)&gs->Bsh[k][tn];
            ull bp0 = pack2(bq.x, bq.y), bp1 = pack2(bq.z, bq.w);
#pragma unroll
            for (int i = 0; i < 4; i++) {
                float a = gs->As[k][tm + i];
                ull p = pack2(a, a);
                acc[i][0] = fma2(p, bp0, acc[i][0]);
                acc[i][1] = fma2(p, bp1, acc[i][1]);
            }
        }
        __syncthreads();
    }
#pragma unroll
    for (int i = 0; i < 4; i++) {
        float2 v0 = unpack2(acc[i][0]), v1 = unpack2(acc[i][1]);
        gs->Ts[tm+i][tn+0] = v0.x + bb[bn + tn + 0];
        gs->Ts[tm+i][tn+1] = v0.y + bb[bn + tn + 1];
        gs->Ts[tm+i][tn+2] = v1.x + bb[bn + tn + 2];
        gs->Ts[tm+i][tn+3] = v1.y + bb[bn + tn + 3];
    }
    __syncthreads();
    int mm = tid & 63, q = tid >> 6;
#pragma unroll
    for (int p = 0; p < 16; p++) {
        int nl = p*4 + q;
        g_zx[((size_t)t*Z4H + bn + nl)*64 + mm] = gs->Ts[mm][nl];
    }
}

// keys/P tile: out[bm..][bn..] = memory[2048x1024] @ B[1024x512]
__device__ void p_kp(GSmem* gs, int r, int tid,
                     const float* __restrict__ A, const float* __restrict__ Bm,
                     float* __restrict__ outp) {
    int bn = (r & 7) * 64, bm = (r >> 3) * 64;
    int tm = (tid >> 4) * 4, tn = (tid & 15) * 4;
    ull acc[4][2];
#pragma unroll
    for (int i = 0; i < 4; i++) { acc[i][0] = 0ull; acc[i][1] = 0ull; }
    for (int kb = 0; kb < MD; kb += 16) {
        int m = tid >> 2, ks = (tid & 3) * 4;
        float4 a4 = *(const float4*)(A + (size_t)(bm + m)*MD + kb + ks);
        gs->As[ks+0][m] = a4.x; gs->As[ks+1][m] = a4.y;
        gs->As[ks+2][m] = a4.z; gs->As[ks+3][m] = a4.w;
        int kl = tid >> 4, c = (tid & 15) * 4;
        *(float4*)&gs->Bsh[kl][c] = *(const float4*)(Bm + (size_t)(kb + kl)*HH + bn + c);
        __syncthreads();
#pragma unroll
        for (int k = 0; k < 16; k++) {
            float4 bq = *(const float4*)&gs->Bsh[k][tn];
            ull bp0 = pack2(bq.x, bq.y), bp1 = pack2(bq.z, bq.w);
#pragma unroll
            for (int i = 0; i < 4; i++) {
                float a = gs->As[k][tm + i];
                ull p = pack2(a, a);
                acc[i][0] = fma2(p, bp0, acc[i][0]);
                acc[i][1] = fma2(p, bp1, acc[i][1]);
            }
        }
        __syncthreads();
    }
#pragma unroll
    for (int i = 0; i < 4; i++) {
        float2 v0 = unpack2(acc[i][0]), v1 = unpack2(acc[i][1]);
        float4 o; o.x = v0.x; o.y = v0.y; o.z = v1.x; o.w = v1.y;
        *(float4*)(outp + (size_t)(bm + tm + i)*HH + bn + tn) = o;
    }
}

// ----------------------------- loop path ---------------------------------------
#define AS_OFF   0          // float [2][64][68]  (row stride 272B), 34816
#define BS2_OFF  34816      // ull   [2][8][64],  8192
#define BQI_OFF  43008      // ull   [2][4][64],  4096
#define QS_OFF   47104      // float[512]
#define VS_OFF   49152      // float[512]
#define SC_OFF   51200      // float[32]
#define AL_OFF   51328      // float[32]

__device__ void loop_path(char* smem, const float* __restrict__ vvec) {
    const uint32_t sb = smem_u32(smem);
    float* qs  = (float*)(smem + QS_OFF);
    float* vs  = (float*)(smem + VS_OFF);
    float* sc2 = (float*)(smem + SC_OFF);
    float* al2 = (float*)(smem + AL_OFF);

    const int j = blockIdx.x;
    const int tid = threadIdx.x;
    const int m  = tid & 63;
    const int hq = tid >> 6;          // 0..3
    const int base = j << 2;          // block's 4 h/n columns
    const int sub = j & 7;

    int a_mm[4], a_kq[4];
#pragma unroll
    for (int u = 0; u < 4; u++) { int e = tid + 256*u; a_mm[u] = e & 63; a_kq[u] = e >> 6; }
    const int b_pr = tid >> 5;        // 0..7
    const int b_c16 = tid & 31;
    const int b_gp = b_pr >> 2, b_hq2 = b_pr & 3;
    const size_t b_srcrow = (size_t)(b_gp*512 + base + b_hq2) * 1024;   // ull units
    const int q_row = (tid >> 5) & 3;
    const size_t q_srcrow = (size_t)(base + q_row) * HH;

    unsigned want = 0;

    for (int t = 0; t < TT; t++) {
        const int cur = t & 1, nxt = cur ^ 1;

        // ================= phase A: z GEMM (K=1024) + gates =================
        {
            ull acc0 = 0ull, acc1 = 0ull;
            {
                const float* asrc = g_aprev;   // kb=0 < 512
#pragma unroll
                for (int u = 0; u < 4; u++)
                    cpasync16(sb + AS_OFF + a_mm[u]*272 + a_kq[u]*16,
                              asrc + (size_t)a_mm[u]*HH + a_kq[u]*4);
                cpasync16(sb + BS2_OFF + b_pr*512 + b_c16*16,
                          g_W2I + b_srcrow + b_c16*2);
                cp_commit();
            }
            for (int c = 0; c < 16; c++) {
                const int buf = c & 1;
                if (c + 1 < 16) {
                    const int kb = (c + 1) * 64;
                    const int nb = (c + 1) & 1;
                    const float* asrc = (kb < 512) ? (g_aprev + kb)
                                                   : (&g_h[cur][0] + (kb - 512));
#pragma unroll
                    for (int u = 0; u < 4; u++)
                        cpasync16(sb + AS_OFF + nb*17408 + a_mm[u]*272 + a_kq[u]*16,
                                  asrc + (size_t)a_mm[u]*HH + a_kq[u]*4);
                    cpasync16(sb + BS2_OFF + nb*4096 + b_pr*512 + b_c16*16,
                              g_W2I + b_srcrow + kb + b_c16*2);
                    cp_commit();
                    cp_wait1();
                } else {
                    cp_wait0();
                }
                __syncthreads();
                const char* asb = smem + AS_OFF + buf*17408 + m*272;
                const char* b0b = smem + BS2_OFF + buf*4096 + hq*512;
                const char* b1b = b0b + 4*512;
#pragma unroll
                for (int k4 = 0; k4 < 16; k4++) {
                    float4 a4 = *(const float4*)(asb + k4*16);
                    ulonglong2 p00 = *(const ulonglong2*)(b0b + k4*32);
                    ulonglong2 p01 = *(const ulonglong2*)(b0b + k4*32 + 16);
                    ulonglong2 p10 = *(const ulonglong2*)(b1b + k4*32);
                    ulonglong2 p11 = *(const ulonglong2*)(b1b + k4*32 + 16);
                    acc0 = fma2(pack2(a4.x, a4.x), p00.x, acc0);
                    acc1 = fma2(pack2(a4.x, a4.x), p10.x, acc1);
                    acc0 = fma2(pack2(a4.y, a4.y), p00.y, acc0);
                    acc1 = fma2(pack2(a4.y, a4.y), p10.y, acc1);
                    acc0 = fma2(pack2(a4.z, a4.z), p01.x, acc0);
                    acc1 = fma2(pack2(a4.z, a4.z), p11.x, acc1);
                    acc0 = fma2(pack2(a4.w, a4.w), p01.y, acc0);
                    acc1 = fma2(pack2(a4.w, a4.w), p11.y, acc1);
                }
                __syncthreads();
            }
            const int h = base + hq;
            float2 v0 = unpack2(acc0);   // (i, f)
            float2 v1 = unpack2(acc1);   // (g, o)
            const size_t zb = ((size_t)t*Z4H)*64 + m;
            float zi = v0.x + g_zx[zb + (size_t)h*64];
            float zf = v0.y + g_zx[zb + (size_t)(512 + h)*64];
            float zg = v1.x + g_zx[zb + (size_t)(1024 + h)*64];
            float zo = v1.y + g_zx[zb + (size_t)(1536 + h)*64];
            float ii = 1.f/(1.f + expf(-zi));
            float ff = 1.f/(1.f + expf(-zf));
            float oo = 1.f/(1.f + expf(-zo));
            float c2 = ff*g_cT[h*64 + m] + ii*tanhf(zg);
            float h2 = oo*tanhf(c2);
            g_cT[h*64 + m] = c2;
            __stcg(&g_h[nxt][m*HH + h], h2);
        }
        want++; gbar2(want, sub, 16u, true);

        // ============ phase BE: q = h2@WqT, e = h2@WaT (paired weights) ======
        {
            float accq = 0.f, acce = 0.f;
            {
#pragma unroll
                for (int u = 0; u < 4; u++)
                    cpasync16(sb + AS_OFF + a_mm[u]*272 + a_kq[u]*16,
                              &g_h[nxt][(size_t)a_mm[u]*HH + a_kq[u]*4]);
                if (tid < 128)
                    cpasync16(sb + BQI_OFF + q_row*512 + b_c16*16,
                              g_WQAI + q_srcrow + b_c16*2);
                cp_commit();
            }
            for (int c = 0; c < 8; c++) {
                const int buf = c & 1;
                if (c + 1 < 8) {
                    const int kb = (c + 1) * 64;
                    const int nb = (c + 1) & 1;
#pragma unroll
                    for (int u = 0; u < 4; u++)
                        cpasync16(sb + AS_OFF + nb*17408 + a_mm[u]*272 + a_kq[u]*16,
                                  &g_h[nxt][(size_t)a_mm[u]*HH + kb + a_kq[u]*4]);
                    if (tid < 128)
                        cpasync16(sb + BQI_OFF + nb*2048 + q_row*512 + b_c16*16,
                                  g_WQAI + q_srcrow + kb + b_c16*2);
                    cp_commit();
                    cp_wait1();
                } else {
                    cp_wait0();
                }
                __syncthreads();
                const char* asb = smem + AS_OFF + buf*17408 + m*272;
                const char* qb  = smem + BQI_OFF + buf*2048 + hq*512;
#pragma unroll
                for (int k4 = 0; k4 < 16; k4++) {
                    float4 a4 = *(const float4*)(asb + k4*16);
                    ulonglong2 w0 = *(const ulonglong2*)(qb + k4*32);
                    ulonglong2 w1 = *(const ulonglong2*)(qb + k4*32 + 16);
                    float2 f0 = unpack2(w0.x), f1 = unpack2(w0.y);
                    float2 f2 = unpack2(w1.x), f3 = unpack2(w1.y);
                    accq += a4.x*f0.x; acce += a4.x*f0.y;
                    accq += a4.y*f1.x; acce += a4.y*f1.y;
                    accq += a4.z*f2.x; acce += a4.z*f2.y;
                    accq += a4.w*f3.x; acce += a4.w*f3.y;
                }
                __syncthreads();
            }
            __stcg(&g_q[m*HH + base + hq], accq);
            __stcg(&g_e[m*HH + base + hq], acce);
        }
        want++; gbar2(want, sub, 16u, true);

        // ====== phase CD: scores + softmax + ctx + attn2 (blocks j<64) ======
        if (j < BB) {
            const int b = j;
            for (int i = tid; i < HH; i += 256) {
                qs[i] = __ldcg(&g_q[b*HH + i]);
                vs[i] = vvec[i];
            }
            __syncthreads();
            int w = tid >> 5, lane = tid & 31;
#pragma unroll
            for (int si = 0; si < 4; si++) {
                int s = (w << 2) + si;
                const float* kp = g_keys + (size_t)(b*SS + s)*HH;
                float acc = 0.f;
                for (int h = lane; h < HH; h += 32)
                    acc += tanh_a(kp[h] + qs[h]) * vs[h];
#pragma unroll
                for (int off = 16; off; off >>= 1)
                    acc += __shfl_down_sync(0xffffffffu, acc, off);
                if (lane == 0) sc2[s] = acc;
            }
            __syncthreads();
            if (tid < SS) {
                float x = sc2[tid];
                float mx = x;
#pragma unroll
                for (int off = 16; off; off >>= 1) mx = fmaxf(mx, __shfl_xor_sync(0xffffffffu, mx, off));
                float e = expf(x - mx);
                float sm = e;
#pragma unroll
                for (int off = 16; off; off >>= 1) sm += __shfl_xor_sync(0xffffffffu, sm, off);
                al2[tid] = e / sm;
            }
            __syncthreads();
            {
                int n0 = tid * 2;
                float acc0 = 0.f, acc1 = 0.f;
#pragma unroll
                for (int s = 0; s < SS; s++) {
                    float2 pv = *(const float2*)&g_P[(size_t)(b*SS + s)*HH + n0];
                    acc0 += al2[s] * pv.x;
                    acc1 += al2[s] * pv.y;
                }
                float2 ev = __ldcg((const float2*)&g_e[b*HH + n0]);
                float v0 = ev.x + acc0;
                float v1 = ev.y + acc1;
                float2 av; av.x = v0; av.y = v1;
                __stcg((float2*)&g_aprev[b*HH + n0], av);
                __half h0b = __float2half(v0);
                __half h1b = __float2half(v1);
                size_t ar = ((size_t)(t*BB + b))*HH + n0;
                unsigned short h0u = *(unsigned short*)&h0b, h1u = *(unsigned short*)&h1b;
                __stcg((unsigned*)(g_Ah + ar), (unsigned)h0u | ((unsigned)h1u << 16));
            }
        }
        want++; gbar2(want, sub, 8u, j < BB);   // publishes g_gen = 3*(t+1)
    }
}

// ----------------------------- mma tile ----------------------------------------
__device__ void mma_tile(char* smem, int bm, int bn,
                         const float* __restrict__ bias, float* __restrict__ C) {
    const uint32_t sb = smem_u32(smem);
    const int tid = threadIdx.x;
    const int wid = tid >> 5, lane = tid & 31;
    const int warpM = wid >> 2, warpN = wid & 3;

    float acc[4][4][4];
#pragma unroll
    for (int i = 0; i < 4; i++)
#pragma unroll
        for (int jj = 0; jj < 4; jj++)
#pragma unroll
            for (int q = 0; q < 4; q++) acc[i][jj][q] = 0.f;

    auto load_stage = [&](int st, int kt) {
        uint32_t base = sb + st * STAGEB;
        const int k0 = kt * 32;
#pragma unroll
        for (int i = 0; i < 2; i++) {
            int c = tid + 256*i;
            int row = c >> 2, ch = c & 3;
            uint32_t so = (uint32_t)(row*ROWB + ch*16);
            size_t gA = (size_t)(bm + row)*HH + k0 + ch*8;
            size_t gB = (size_t)(bn + row)*HH + k0 + ch*8;
            cpasync16(base + 0*TILEB + so, g_Ah + gA);
            cpasync16(base + 1*TILEB + so, g_Bh + gB);
        }
        cp_commit();
    };

    load_stage(0, 0);

    const int jA = lane >> 3;
    const int rowA = (jA & 1)*8 + (lane & 7);
    const int colA = (jA >> 1)*16;
    const int rowB = lane & 7;
    const int colB = ((lane >> 3) & 1)*16;

    for (int kt = 0; kt < 16; kt++) {
        if (kt < 15) { load_stage((kt + 1) & 1, kt + 1); cp_wait1(); }
        else         { cp_wait0(); }
        __syncthreads();

        uint32_t base = sb + (kt & 1) * STAGEB;
        uint32_t sAh = base, sBh = base + TILEB;

#pragma unroll
        for (int ks = 0; ks < 2; ks++) {
            uint32_t bh[4][2];
#pragma unroll
            for (int nt = 0; nt < 4; nt++) {
                uint32_t off = (uint32_t)((warpN*32 + nt*8 + rowB)*ROWB + ks*32 + colB);
                ldsm2(bh[nt], sBh + off);
            }
#pragma unroll
            for (int mt = 0; mt < 4; mt++) {
                uint32_t ah[4];
                uint32_t off = (uint32_t)((warpM*64 + mt*16 + rowA)*ROWB + ks*32 + colA);
                ldsm4(ah, sAh + off);
#pragma unroll
                for (int nt = 0; nt < 4; nt++) {
                    mma16816(acc[mt][nt], ah, bh[nt]);
                }
            }
        }
        __syncthreads();
    }

    // epilogue: rows are t*64+b -> C row b*31+t
    const int g = lane >> 2, tg = lane & 3;
#pragma unroll
    for (int mt = 0; mt < 4; mt++) {
        int row0 = bm + warpM*64 + mt*16 + g;
        int row1 = row0 + 8;
#pragma unroll
        for (int nt = 0; nt < 4; nt++) {
            int col = bn + warpN*32 + nt*8 + tg*2;
            if (col >= VV) continue;
            float2 bi = *(const float2*)(bias + col);
            if (row0 < BB*TT) {
                int tt = row0 >> 6, b = row0 & 63;
                float2 o; o.x = acc[mt][nt][0] + bi.x; o.y = acc[mt][nt][1] + bi.y;
                *(float2*)(C + ((size_t)(b*TT + tt))*VV + col) = o;
            }
            if (row1 < BB*TT) {
                int tt = row1 >> 6, b = row1 & 63;
                float2 o; o.x = acc[mt][nt][2] + bi.x; o.y = acc[mt][nt][3] + bi.y;
                *(float2*)(C + ((size_t)(b*TT + tt))*VV + col) = o;
            }
        }
    }
}

// ----------------------------- the single fused kernel -------------------------
__global__ void __launch_bounds__(256, 2) k_all(
        const void* __restrict__ dec,
        const float* __restrict__ memory,
        const float* __restrict__ h0,
        const float* __restrict__ c0,
        const float* __restrict__ emb,
        const float* __restrict__ Wk,
        const float* __restrict__ Wr,
        const float* __restrict__ bb,
        const float* __restrict__ Wq,
        const float* __restrict__ Wa,
        const float* __restrict__ Wm,
        const float* __restrict__ Wfc,
        const float* __restrict__ vvec,
        const float* __restrict__ bias,
        float* __restrict__ C) {
    extern __shared__ char smem[];
    __shared__ int s_idx;
    const int tid = threadIdx.x;
    PSmem* ps = (PSmem*)smem;
    GSmem* gs = (GSmem*)smem;

    // ---------------- queue 1: loop prerequisites (all blocks) ----------------
    for (;;) {
        if (tid == 0) s_idx = (int)atomicAdd(&g_ptile, 1u);
        __syncthreads();
        int i = s_idx;
        if (i >= P1TOTAL) break;
        if (i < PB_TW2)       p_init(i, tid, h0, c0);
        else if (i < PB_TWQ)  p_tw2(ps, i - PB_TW2, tid, Wk, Wr);
        else if (i < PB_ZX)   p_twq(ps, i - PB_TWQ, tid, Wq, Wa);
        else if (i < PB_KEY)  p_zx(gs, i - PB_ZX, tid, dec, emb, Wk, bb);
        else if (i < PB_P)    p_kp(gs, i - PB_KEY, tid, memory, Wm, g_keys);
        else                  p_kp(gs, i - PB_P, tid, memory, Wa + HH*HH, g_P);
        __syncthreads();
    }
    __syncthreads();
    if (tid == 0) {
        __threadfence();
        atom_add_ar(&g_pdone, 1u);
    }

    if (blockIdx.x < NBLK) {
        // loop blocks: wait for all prereq tiles (all 296 blocks through queue 1)
        if (tid == 0) {
            while (ld_acq(&g_pdone) < GRID_FUSED) { }
        }
        __syncthreads();
        loop_path(smem, vvec);
    } else {
        // worker blocks: convert Wfc -> fp16 concurrently with loop startup
        for (;;) {
            if (tid == 0) s_idx = (int)atomicAdd(&g_ptile2, 1u);
            __syncthreads();
            int i = s_idx;
            if (i >= NT_CVTB) break;
            p_cvtB(ps, i, tid, Wfc);
            __syncthreads();
        }
        __syncthreads();
        if (tid == 0) {
            __threadfence();
            atom_add_ar(&g_cdone, 1u);
        }
    }

    // ---------------- mma worker pool (all blocks; gated on cvtB done) -------
    if (tid == 0) {
        while (ld_acq(&g_cdone) < NWORK)
            asm volatile("nanosleep.u32 256;");
    }
    __syncthreads();

    for (;;) {
        if (tid == 0) s_idx = (int)atomicAdd(&g_tile, 1u);
        __syncthreads();
        int idx = s_idx;
        if (idx >= NTILES) break;
        int by = idx / NXB, bx = idx - by*NXB;
        if (tid == 0) {
            int tmaxv = 2*by + 1; if (tmaxv > TT-1) tmaxv = TT-1;
            unsigned need = 3u * (unsigned)(tmaxv + 1);
            while (ld_rlx(&g_gen2) < need)
                asm volatile("nanosleep.u32 1024;");
            (void)ld_acq(&g_gen2);
        }
        __syncthreads();
        mma_tile(smem, by*128, bx*128, bias, C);
        __syncthreads();
    }
}

// ----------------------------- launch sequence --------------------------------
extern "C" void kernel_launch(void* const* d_in, const int* in_sizes, int n_in,
                              void* d_out, int out_size) {
    const void*  dec    = d_in[0];
    const float* memory = (const float*)d_in[1];
    const float* h0     = (const float*)d_in[2];
    const float* c0     = (const float*)d_in[3];
    const float* emb    = (const float*)d_in[4];
    const float* Wk     = (const float*)d_in[5];
    const float* Wr     = (const float*)d_in[6];
    const float* bb     = (const float*)d_in[7];
    const float* Wm     = (const float*)d_in[8];
    const float* Wq     = (const float*)d_in[9];
    const float* vv     = (const float*)d_in[10];
    const float* Wa     = (const float*)d_in[11];
    const float* Wfc    = (const float*)d_in[12];
    const float* bfc    = (const float*)d_in[13];
    float* out = (float*)d_out;

    cudaFuncSetAttribute(k_all, cudaFuncAttributeMaxDynamicSharedMemorySize, SMEM_FUSED);

    k_rst<<<1, 32>>>();
    k_all<<<GRID_FUSED, 256, SMEM_FUSED>>>(dec, memory, h0, c0, emb, Wk, Wr, bb,
                                           Wq, Wa, Wm, Wfc, vv, bfc, out);
}

// round 17
// speedup vs baseline: 1.0727x; 1.0727x over previous
#include <cuda_runtime.h>
#include <cuda_fp16.h>
#include <cstdint>
#include <cstddef>

#define BB 64
#define TT 31
#define SS 32
#define VV 34004
#define EE 300
#define HH 512
#define MD 1024
#define BH (BB*HH)
#define Z4H 2048
#define NBLK 128
#define NPAD 34048            // 266 * 128
#define MPAD 2048
#define NXB 266
#define NTILES (16*NXB)       // 4256
#define GRID_FUSED 296
#define NWORK (GRID_FUSED - NBLK)   // 168
#define TSPLIT 8

// prologue queue 1 (loop prereqs)
#define NT_INIT 16
#define NT_TW2  1024
#define NT_TWQ  256
#define NT_ZX   992
#define NT_KEY  256
#define NT_P    256
#define PB_INIT 0
#define PB_TW2  (PB_INIT + NT_INIT)      // 16
#define PB_TWQ  (PB_TW2 + NT_TW2)        // 1040
#define PB_ZX   (PB_TWQ + NT_TWQ)        // 1296
#define PB_KEY  (PB_ZX + NT_ZX)          // 2288
#define PB_P    (PB_KEY + NT_KEY)        // 2544
#define P1TOTAL (PB_P + NT_P)            // 2800
// queue 2a: Wcomb (128) + PZ (512); queue 2b: cvtB
#define NT_WCOMB 128
#define NT_PZ    512
#define Q2A_TOTAL (NT_WCOMB + NT_PZ)     // 640
#define NT_CVTB 4256

typedef unsigned long long ull;

// ----------------------------- device scratch --------------------------------
__device__ __align__(16) float g_keys[BB*SS*HH];
__device__ __align__(16) float g_P[BB*SS*HH];
__device__ __align__(16) float g_zx[BB*TT*Z4H];        // [t][n][m] transposed
__device__ __align__(16) ull   g_W2I[1024*1024];       // [gp*512+h][k] pairs, K=1024 (t<TSPLIT)
__device__ __align__(16) ull   g_WcombI[1024*512];     // [gp*512+h][k] pairs, K=512  (t>=TSPLIT)
__device__ __align__(16) ull   g_PZI[(size_t)2*512*32*64];  // [(gp*512+h)*32+s]*64+b, 16 MB
__device__ __align__(16) ull   g_WQAI[512*512];        // [n][k] (Wq,Wa) pairs
__device__ __align__(16) float g_h[2][BH];             // [m][h]
__device__ __align__(16) float g_cT[HH*BB];            // [h][m]
__device__ __align__(16) float g_aprev[BH];            // [m][n]  (used t<TSPLIT)
__device__ __align__(16) float g_q[BH];
__device__ __align__(16) float g_e[BH];
__device__ __align__(16) float g_al[BB*SS];            // softmax weights (latest step)
__device__ __align__(16) __half g_Ah[MPAD*HH];         // rows t*64+b (fp16)
__device__ __align__(16) __half g_Bh[(size_t)NPAD*HH]; // fp16
__device__ unsigned g_cnt;
__device__ unsigned g_gen;
__device__ unsigned g_gen2;
__device__ unsigned g_tile;
__device__ unsigned g_ptile;
__device__ unsigned g_ptile2;
__device__ unsigned g_ptile3;
__device__ unsigned g_pdone;
__device__ unsigned g_zdone;
__device__ unsigned g_cdone;

// ----------------------------- scalar helpers --------------------------------
__device__ __forceinline__ ull pack2(float x, float y) {
    ull r; asm("mov.b64 %0, {%1,%2};" : "=l"(r) : "f"(x), "f"(y)); return r;
}
__device__ __forceinline__ ull fma2(ull a, ull b, ull c) {
    ull d; asm("fma.rn.f32x2 %0, %1, %2, %3;" : "=l"(d) : "l"(a), "l"(b), "l"(c)); return d;
}
__device__ __forceinline__ float2 unpack2(ull a) {
    float2 f; asm("mov.b64 {%0,%1}, %2;" : "=f"(f.x), "=f"(f.y) : "l"(a)); return f;
}
__device__ __forceinline__ float tanh_a(float x) {
    float y; asm("tanh.approx.f32 %0, %1;" : "=f"(y) : "f"(x)); return y;
}
__device__ __forceinline__ uint32_t smem_u32(const void* p) {
    uint32_t a;
    asm("{ .reg .u64 t; cvta.to.shared.u64 t, %1; cvt.u32.u64 %0, t; }" : "=r"(a) : "l"(p));
    return a;
}
__device__ __forceinline__ unsigned ld_acq(const unsigned* p) {
    unsigned v; asm volatile("ld.acquire.gpu.global.u32 %0, [%1];" : "=r"(v) : "l"(p) : "memory"); return v;
}
__device__ __forceinline__ unsigned ld_rlx(const unsigned* p) {
    unsigned v; asm volatile("ld.relaxed.gpu.global.u32 %0, [%1];" : "=r"(v) : "l"(p) : "memory"); return v;
}
__device__ __forceinline__ void st_rel(unsigned* p, unsigned v) {
    asm volatile("st.release.gpu.global.u32 [%0], %1;" :: "l"(p), "r"(v) : "memory");
}
__device__ __forceinline__ void st_rlx(unsigned* p, unsigned v) {
    asm volatile("st.relaxed.gpu.global.u32 [%0], %1;" :: "l"(p), "r"(v) : "memory");
}
__device__ __forceinline__ unsigned atom_add_ar(unsigned* p, unsigned v) {
    unsigned o; asm volatile("atom.acq_rel.gpu.global.add.u32 %0, [%1], %2;"
                             : "=r"(o) : "l"(p), "r"(v) : "memory"); return o;
}

// flat grid barrier (R14 version — fastest measured)
__device__ __forceinline__ void gbar() {
    __syncthreads();
    if (threadIdx.x == 0) {
        unsigned g = ld_acq(&g_gen);
        unsigned a = atom_add_ar(&g_cnt, 1u);
        if (a == NBLK - 1) {
            st_rlx(&g_cnt, 0u);
            st_rel(&g_gen, g + 1u);
            st_rel(&g_gen2, g + 1u);
        } else {
            while (ld_rlx(&g_gen) == g) { }
            (void)ld_acq(&g_gen);
        }
    }
    __syncthreads();
}

// ----------------------------- reset (per graph replay) ------------------------
__global__ void k_rst() {
    if (threadIdx.x == 0) {
        g_cnt = 0; g_gen = 0; g_gen2 = 0; g_tile = 0;
        g_ptile = 0; g_ptile2 = 0; g_ptile3 = 0;
        g_pdone = 0; g_zdone = 0; g_cdone = 0;
    }
}

// ----------------------------- async primitives --------------------------------
__device__ __forceinline__ void cpasync16(uint32_t saddr, const void* g) {
    asm volatile("cp.async.cg.shared.global [%0], [%1], 16;" :: "r"(saddr), "l"(g));
}
__device__ __forceinline__ void cp_commit() { asm volatile("cp.async.commit_group;"); }
__device__ __forceinline__ void cp_wait1()  { asm volatile("cp.async.wait_group 1;"); }
__device__ __forceinline__ void cp_wait0()  { asm volatile("cp.async.wait_group 0;"); }

// ----------------------------- mma primitives ---------------------------------
#define ROWB 80
#define TILEB (128*ROWB)        // 10240
#define STAGEB (2*TILEB)        // 20480 (Ah, Bh)
#define SMEM_FUSED 61440

__device__ __forceinline__ void ldsm4(uint32_t* r, uint32_t addr) {
    asm volatile("ldmatrix.sync.aligned.m8n8.x4.shared.b16 {%0,%1,%2,%3}, [%4];"
                 : "=r"(r[0]), "=r"(r[1]), "=r"(r[2]), "=r"(r[3]) : "r"(addr));
}
__device__ __forceinline__ void ldsm2(uint32_t* r, uint32_t addr) {
    asm volatile("ldmatrix.sync.aligned.m8n8.x2.shared.b16 {%0,%1}, [%2];"
                 : "=r"(r[0]), "=r"(r[1]) : "r"(addr));
}
__device__ __forceinline__ void mma16816(float* c, const uint32_t* a, const uint32_t* b) {
    asm volatile("mma.sync.aligned.m16n8k16.row.col.f32.f16.f16.f32 "
                 "{%0,%1,%2,%3}, {%4,%5,%6,%7}, {%8,%9}, {%0,%1,%2,%3};"
                 : "+f"(c[0]), "+f"(c[1]), "+f"(c[2]), "+f"(c[3])
                 : "r"(a[0]), "r"(a[1]), "r"(a[2]), "r"(a[3]), "r"(b[0]), "r"(b[1]));
}

// ----------------------------- prologue tile bodies ---------------------------
struct PSmem {                 // transpose tiles
    float t0[32][33];
    float t1[32][33];
};
struct GSmem {                 // fp32 GEMM tiles
    float As[16][65];
    float Bsh[16][64];
    float Ts[64][65];          // zx only
};
struct WSmem {                 // dual-column GEMM tiles (wcomb / pz)
    float As[16][65];
    ull   Bsu[16][64];
};

__device__ void p_init(int i, int tid, const float* h0, const float* c0) {
#pragma unroll
    for (int u = 0; u < 8; u++) {
        int idx = i*2048 + u*256 + tid;
        int b = idx >> 9, h = idx & 511;
        g_h[0][idx] = h0[idx];
        g_cT[h*BB + b] = c0[idx];
        g_aprev[idx] = 0.f;
        size_t o = (size_t)(BB*TT)*HH + idx;
        g_Ah[o] = __float2half(0.f);
    }
}

__device__ void p_tw2(PSmem* ps, int r, int tid,
                      const float* __restrict__ Wk, const float* __restrict__ Wr) {
    int gp = r >> 9, r2 = r & 511;
    int h0 = (r2 >> 5) * 32, k0 = (r2 & 31) * 32;
    int tx = tid & 31, ty = tid >> 5;
#pragma unroll
    for (int ii = 0; ii < 4; ii++) {
        int kk = ty + 8*ii;
        int kg = k0 + kk;
        int n0 = gp*1024 + h0 + tx;
        float a, b;
        if (kg < 512) {
            a = Wk[(size_t)(300 + kg)*Z4H + n0];
            b = Wk[(size_t)(300 + kg)*Z4H + n0 + 512];
        } else {
            a = Wr[(size_t)(kg - 512)*Z4H + n0];
            b = Wr[(size_t)(kg - 512)*Z4H + n0 + 512];
        }
        ps->t0[kk][tx] = a; ps->t1[kk][tx] = b;
    }
    __syncthreads();
#pragma unroll
    for (int ii = 0; ii < 4; ii++) {
        int nl = ty + 8*ii;
        g_W2I[(size_t)(gp*512 + h0 + nl)*1024 + k0 + tx] = pack2(ps->t0[tx][nl], ps->t1[tx][nl]);
    }
}

__device__ void p_twq(PSmem* ps, int r, int tid,
                      const float* __restrict__ Wq, const float* __restrict__ Wa) {
    int k0 = (r & 15) * 32, n0 = (r >> 4) * 32;
    int tx = tid & 31, ty = tid >> 5;
#pragma unroll
    for (int ii = 0; ii < 4; ii++) {
        int kk = ty + 8*ii;
        ps->t0[kk][tx] = Wq[(size_t)(k0 + kk)*HH + n0 + tx];
        ps->t1[kk][tx] = Wa[(size_t)(k0 + kk)*HH + n0 + tx];
    }
    __syncthreads();
#pragma unroll
    for (int ii = 0; ii < 4; ii++) {
        int nl = ty + 8*ii;
        g_WQAI[(size_t)(n0 + nl)*HH + k0 + tx] = pack2(ps->t0[tx][nl], ps->t1[tx][nl]);
    }
}

__device__ void p_cvtB(PSmem* ps, int r, int tid, const float* __restrict__ Wfc) {
    int ng = r >> 2, kg = r & 3;
    int n0 = ng * 32;
    int tx = tid & 31, ty = tid >> 5;
#pragma unroll
    for (int sub = 0; sub < 4; sub++) {
        int k0 = kg*128 + sub*32;
#pragma unroll
        for (int ii = 0; ii < 4; ii++) {
            int kk = ty + 8*ii;
            int n = n0 + tx;
            ps->t0[kk][tx] = (n < VV) ? Wfc[(size_t)(k0 + kk)*VV + n] : 0.f;
        }
        __syncthreads();
#pragma unroll
        for (int ii = 0; ii < 4; ii++) {
            int nl = ty + 8*ii;
            float v = ps->t0[tx][nl];
            size_t o = (size_t)(n0 + nl)*HH + k0 + tx;
            g_Bh[o] = __float2half(v);
        }
        __syncthreads();
    }
}

// zx tile
__device__ void p_zx(GSmem* gs, int r, int tid,
                     const void* __restrict__ dec, const float* __restrict__ emb,
                     const float* __restrict__ Wk, const float* __restrict__ bb) {
    int t = r >> 5, bn = (r & 31) * 64;
    const long long* p64 = (const long long*)dec;
    bool is64 = true;
#pragma unroll
    for (int i = 0; i < 4; i++) { long long v = p64[i]; if (v < 0 || v >= VV) is64 = false; }

    int tm = (tid >> 4) * 4, tn = (tid & 15) * 4;
    int m = tid >> 2, ks4 = (tid & 3) * 4;
    long long tok = is64 ? p64[m*TT + t] : (long long)((const int*)dec)[m*TT + t];
    const float* arow = emb + (size_t)tok * EE;

    ull acc[4][2];
#pragma unroll
    for (int i = 0; i < 4; i++) { acc[i][0] = 0ull; acc[i][1] = 0ull; }
    for (int kb = 0; kb < EE; kb += 16) {
        float4 a4 = make_float4(0.f, 0.f, 0.f, 0.f);
        if (kb + ks4 < EE) a4 = *(const float4*)(arow + kb + ks4);
        gs->As[ks4+0][m] = a4.x; gs->As[ks4+1][m] = a4.y;
        gs->As[ks4+2][m] = a4.z; gs->As[ks4+3][m] = a4.w;
        int kl = tid >> 4, c = (tid & 15) * 4;
        float4 b4 = make_float4(0.f, 0.f, 0.f, 0.f);
        if (kb + kl < EE) b4 = *(const float4*)(Wk + (size_t)(kb + kl)*Z4H + bn + c);
        *(float4*)&gs->Bsh[kl][c] = b4;
        __syncthreads();
#pragma unroll
        for (int k = 0; k < 16; k++) {
            float4 bq = *(const float4*)&gs->Bsh[k][tn];
            ull bp0 = pack2(bq.x, bq.y), bp1 = pack2(bq.z, bq.w);
#pragma unroll
            for (int i = 0; i < 4; i++) {
                float a = gs->As[k][tm + i];
                ull p = pack2(a, a);
                acc[i][0] = fma2(p, bp0, acc[i][0]);
                acc[i][1] = fma2(p, bp1, acc[i][1]);
            }
        }
        __syncthreads();
    }
#pragma unroll
    for (int i = 0; i < 4; i++) {
        float2 v0 = unpack2(acc[i][0]), v1 = unpack2(acc[i][1]);
        gs->Ts[tm+i][tn+0] = v0.x + bb[bn + tn + 0];
        gs->Ts[tm+i][tn+1] = v0.y + bb[bn + tn + 1];
        gs->Ts[tm+i][tn+2] = v1.x + bb[bn + tn + 2];
        gs->Ts[tm+i][tn+3] = v1.y + bb[bn + tn + 3];
    }
    __syncthreads();
    int mm = tid & 63, q = tid >> 6;
#pragma unroll
    for (int p = 0; p < 16; p++) {
        int nl = p*4 + q;
        g_zx[((size_t)t*Z4H + bn + nl)*64 + mm] = gs->Ts[mm][nl];
    }
}

// keys/P tile
__device__ void p_kp(GSmem* gs, int r, int tid,
                     const float* __restrict__ A, const float* __restrict__ Bm,
                     float* __restrict__ outp) {
    int bn = (r & 7) * 64, bm = (r >> 3) * 64;
    int tm = (tid >> 4) * 4, tn = (tid & 15) * 4;
    ull acc[4][2];
#pragma unroll
    for (int i = 0; i < 4; i++) { acc[i][0] = 0ull; acc[i][1] = 0ull; }
    for (int kb = 0; kb < MD; kb += 16) {
        int m = tid >> 2, ks = (tid & 3) * 4;
        float4 a4 = *(const float4*)(A + (size_t)(bm + m)*MD + kb + ks);
        gs->As[ks+0][m] = a4.x; gs->As[ks+1][m] = a4.y;
        gs->As[ks+2][m] = a4.z; gs->As[ks+3][m] = a4.w;
        int kl = tid >> 4, c = (tid & 15) * 4;
        *(float4*)&gs->Bsh[kl][c] = *(const float4*)(Bm + (size_t)(kb + kl)*HH + bn + c);
        __syncthreads();
#pragma unroll
        for (int k = 0; k < 16; k++) {
            float4 bq = *(const float4*)&gs->Bsh[k][tn];
            ull bp0 = pack2(bq.x, bq.y), bp1 = pack2(bq.z, bq.w);
#pragma unroll
            for (int i = 0; i < 4; i++) {
                float a = gs->As[k][tm + i];
                ull p = pack2(a, a);
                acc[i][0] = fma2(p, bp0, acc[i][0]);
                acc[i][1] = fma2(p, bp1, acc[i][1]);
            }
        }
        __syncthreads();
    }
#pragma unroll
    for (int i = 0; i < 4; i++) {
        float2 v0 = unpack2(acc[i][0]), v1 = unpack2(acc[i][1]);
        float4 o; o.x = v0.x; o.y = v0.y; o.z = v1.x; o.w = v1.y;
        *(float4*)(outp + (size_t)(bm + tm + i)*HH + bn + tn) = o;
    }
}

// Wcomb tile: WcombI[(gp*512+h)][k] = pack2(Wr+WaTop@Wk2 at cols (gp*1024+h, +512))
__device__ void p_wcomb(WSmem* ws, int r, int tid,
                        const float* __restrict__ Wa, const float* __restrict__ Wk,
                        const float* __restrict__ Wr) {
    int gp = r >> 6, kt = (r >> 3) & 7, ht = r & 7;
    int k0 = kt * 64, h0g = ht * 64;
    int tm = (tid >> 4) * 4, tn = (tid & 15) * 4;
    ull acc[4][4];
#pragma unroll
    for (int i = 0; i < 4; i++)
#pragma unroll
        for (int jj = 0; jj < 4; jj++) acc[i][jj] = 0ull;

    for (int a0 = 0; a0 < HH; a0 += 16) {
        int kl = tid >> 2, a4 = (tid & 3) * 4;
        float4 av = *(const float4*)(Wa + (size_t)(k0 + kl)*HH + a0 + a4);
        ws->As[a4+0][kl] = av.x; ws->As[a4+1][kl] = av.y;
        ws->As[a4+2][kl] = av.z; ws->As[a4+3][kl] = av.w;
#pragma unroll
        for (int u = 0; u < 4; u++) {
            int e = tid + 256*u;
            int ali = e >> 6, hl = e & 63;
            size_t wrow = (size_t)(300 + a0 + ali) * Z4H + gp*1024 + h0g + hl;
            ws->Bsu[ali][hl] = pack2(Wk[wrow], Wk[wrow + 512]);
        }
        __syncthreads();
#pragma unroll
        for (int a = 0; a < 16; a++) {
#pragma unroll
            for (int i = 0; i < 4; i++) {
                float aval = ws->As[a][tm + i];
                ull p = pack2(aval, aval);
#pragma unroll
                for (int jj = 0; jj < 4; jj++)
                    acc[i][jj] = fma2(p, ws->Bsu[a][tn + jj], acc[i][jj]);
            }
        }
        __syncthreads();
    }
#pragma unroll
    for (int i = 0; i < 4; i++) {
#pragma unroll
        for (int jj = 0; jj < 4; jj++) {
            int k = k0 + tm + i, h = h0g + tn + jj;
            size_t wrow = (size_t)k * Z4H + gp*1024 + h;
            float2 v = unpack2(acc[i][jj]);
            v.x += Wr[wrow];
            v.y += Wr[wrow + 512];
            g_WcombI[(size_t)(gp*512 + h)*512 + k] = pack2(v.x, v.y);
        }
    }
}

// PZ tile: PZI[((gp*512+h)*32+s)*64+b] = pack2(P@Wk2 at cols (gp*1024+h, +512))
__device__ void p_pz(WSmem* ws, int r, int tid,
                     const float* __restrict__ Wk) {
    int gp = r >> 8, rowt = (r >> 3) & 31, ht = r & 7;
    int r0 = rowt * 64, h0g = ht * 64;
    int tm = (tid >> 4) * 4, tn = (tid & 15) * 4;
    ull acc[4][4];
#pragma unroll
    for (int i = 0; i < 4; i++)
#pragma unroll
        for (int jj = 0; jj < 4; jj++) acc[i][jj] = 0ull;

    for (int a0 = 0; a0 < HH; a0 += 16) {
        int rl = tid >> 2, a4 = (tid & 3) * 4;
        float4 av = *(const float4*)(g_P + (size_t)(r0 + rl)*HH + a0 + a4);
        ws->As[a4+0][rl] = av.x; ws->As[a4+1][rl] = av.y;
        ws->As[a4+2][rl] = av.z; ws->As[a4+3][rl] = av.w;
#pragma unroll
        for (int u = 0; u < 4; u++) {
            int e = tid + 256*u;
            int ali = e >> 6, hl = e & 63;
            size_t wrow = (size_t)(300 + a0 + ali) * Z4H + gp*1024 + h0g + hl;
            ws->Bsu[ali][hl] = pack2(Wk[wrow], Wk[wrow + 512]);
        }
        __syncthreads();
#pragma unroll
        for (int a = 0; a < 16; a++) {
#pragma unroll
            for (int i = 0; i < 4; i++) {
                float aval = ws->As[a][tm + i];
                ull p = pack2(aval, aval);
#pragma unroll
                for (int jj = 0; jj < 4; jj++)
                    acc[i][jj] = fma2(p, ws->Bsu[a][tn + jj], acc[i][jj]);
            }
        }
        __syncthreads();
    }
#pragma unroll
    for (int i = 0; i < 4; i++) {
#pragma unroll
        for (int jj = 0; jj < 4; jj++) {
            int row = r0 + tm + i;
            int b = row >> 5, s = row & 31;
            int h = h0g + tn + jj;
            g_PZI[((size_t)(gp*512 + h)*32 + s)*64 + b] = acc[i][jj];
        }
    }
}

// ----------------------------- loop path ---------------------------------------
#define AS_OFF   0          // float [2][64][68]  (row stride 272B), 34816
#define BS2_OFF  34816      // ull   [2][8][64],  8192
#define BQI_OFF  43008      // ull   [2][4][64],  4096
#define QS_OFF   47104      // float[512]
#define VS_OFF   49152      // float[512]
#define SC_OFF   51200      // float[32]
#define AL_OFF   51328      // float[32]
#define ALSM_OFF 51456      // float[64*33] = 8448 -> end 59904

__device__ void loop_path(char* smem, const float* __restrict__ vvec) {
    const uint32_t sb = smem_u32(smem);
    float* qs   = (float*)(smem + QS_OFF);
    float* vs   = (float*)(smem + VS_OFF);
    float* sc2  = (float*)(smem + SC_OFF);
    float* al2  = (float*)(smem + AL_OFF);
    float* alsm = (float*)(smem + ALSM_OFF);

    const int j = blockIdx.x;
    const int tid = threadIdx.x;
    const int m  = tid & 63;
    const int hq = tid >> 6;          // 0..3
    const int base = j << 2;          // block's 4 h/n columns

    int a_mm[4], a_kq[4];
#pragma unroll
    for (int u = 0; u < 4; u++) { int e = tid + 256*u; a_mm[u] = e & 63; a_kq[u] = e >> 6; }
    const int b_pr = tid >> 5;        // 0..7
    const int b_c16 = tid & 31;
    const int b_gp = b_pr >> 2, b_hq2 = b_pr & 3;
    const size_t b_srcrow  = (size_t)(b_gp*512 + base + b_hq2) * 1024;  // W2I (K=1024)
    const size_t b_srcrow2 = (size_t)(b_gp*512 + base + b_hq2) * 512;   // WcombI (K=512)
    const int q_row = (tid >> 5) & 3;
    const size_t q_srcrow = (size_t)(base + q_row) * HH;
    // PZI row pointers for (h = base+hq, gp 0/1), lane offset m
    const ull* pz0 = g_PZI + (size_t)(base + hq)*32*64 + m;
    const ull* pz1 = g_PZI + (size_t)(512 + base + hq)*32*64 + m;

    for (int t = 0; t < TT; t++) {
        const int cur = t & 1, nxt = cur ^ 1;

        // gate on PZ/Wcomb readiness once
        if (t == TSPLIT) {
            if (tid == 0) {
                while (ld_acq(&g_zdone) < NWORK)
                    asm volatile("nanosleep.u32 256;");
            }
            __syncthreads();
        }

        // ================= phase A: z GEMM + gates =================
        ull acc0 = 0ull, acc1 = 0ull;
        if (t < TSPLIT) {
            // old path: K=1024 (aprev | h) with W2I
            {
                const float* asrc = g_aprev;
#pragma unroll
                for (int u = 0; u < 4; u++)
                    cpasync16(sb + AS_OFF + a_mm[u]*272 + a_kq[u]*16,
                              asrc + (size_t)a_mm[u]*HH + a_kq[u]*4);
                cpasync16(sb + BS2_OFF + b_pr*512 + b_c16*16,
                          g_W2I + b_srcrow + b_c16*2);
                cp_commit();
            }
            for (int c = 0; c < 16; c++) {
                const int buf = c & 1;
                if (c + 1 < 16) {
                    const int kb = (c + 1) * 64;
                    const int nb = (c + 1) & 1;
                    const float* asrc = (kb < 512) ? (g_aprev + kb)
                                                   : (&g_h[cur][0] + (kb - 512));
#pragma unroll
                    for (int u = 0; u < 4; u++)
                        cpasync16(sb + AS_OFF + nb*17408 + a_mm[u]*272 + a_kq[u]*16,
                                  asrc + (size_t)a_mm[u]*HH + a_kq[u]*4);
                    cpasync16(sb + BS2_OFF + nb*4096 + b_pr*512 + b_c16*16,
                              g_W2I + b_srcrow + kb + b_c16*2);
                    cp_commit();
                    cp_wait1();
                } else {
                    cp_wait0();
                }
                __syncthreads();
                const char* asb = smem + AS_OFF + buf*17408 + m*272;
                const char* b0b = smem + BS2_OFF + buf*4096 + hq*512;
                const char* b1b = b0b + 4*512;
#pragma unroll
                for (int k4 = 0; k4 < 16; k4++) {
                    float4 a4 = *(const float4*)(asb + k4*16);
                    ulonglong2 p00 = *(const ulonglong2*)(b0b + k4*32);
                    ulonglong2 p01 = *(const ulonglong2*)(b0b + k4*32 + 16);
                    ulonglong2 p10 = *(const ulonglong2*)(b1b + k4*32);
                    ulonglong2 p11 = *(const ulonglong2*)(b1b + k4*32 + 16);
                    acc0 = fma2(pack2(a4.x, a4.x), p00.x, acc0);
                    acc1 = fma2(pack2(a4.x, a4.x), p10.x, acc1);
                    acc0 = fma2(pack2(a4.y, a4.y), p00.y, acc0);
                    acc1 = fma2(pack2(a4.y, a4.y), p10.y, acc1);
                    acc0 = fma2(pack2(a4.z, a4.z), p01.x, acc0);
                    acc1 = fma2(pack2(a4.z, a4.z), p11.x, acc1);
                    acc0 = fma2(pack2(a4.w, a4.w), p01.y, acc0);
                    acc1 = fma2(pack2(a4.w, a4.w), p11.y, acc1);
                }
                __syncthreads();
            }
        } else {
            // new path: K=512 over h with WcombI, plus K=32 al@PZ term
            // stage al (written by CD of step t-1)
#pragma unroll
            for (int u = 0; u < 8; u++) {
                int idx = u*256 + tid;
                int mi = idx >> 5, si = idx & 31;
                alsm[mi*33 + si] = __ldcg(&g_al[mi*32 + si]);
            }
            {
#pragma unroll
                for (int u = 0; u < 4; u++)
                    cpasync16(sb + AS_OFF + a_mm[u]*272 + a_kq[u]*16,
                              &g_h[cur][(size_t)a_mm[u]*HH + a_kq[u]*4]);
                cpasync16(sb + BS2_OFF + b_pr*512 + b_c16*16,
                          g_WcombI + b_srcrow2 + b_c16*2);
                cp_commit();
            }
            for (int c = 0; c < 8; c++) {
                const int buf = c & 1;
                if (c + 1 < 8) {
                    const int kb = (c + 1) * 64;
                    const int nb = (c + 1) & 1;
#pragma unroll
                    for (int u = 0; u < 4; u++)
                        cpasync16(sb + AS_OFF + nb*17408 + a_mm[u]*272 + a_kq[u]*16,
                                  &g_h[cur][(size_t)a_mm[u]*HH + kb + a_kq[u]*4]);
                    cpasync16(sb + BS2_OFF + nb*4096 + b_pr*512 + b_c16*16,
                              g_WcombI + b_srcrow2 + kb + b_c16*2);
                    cp_commit();
                    cp_wait1();
                } else {
                    cp_wait0();
                }
                __syncthreads();
                const char* asb = smem + AS_OFF + buf*17408 + m*272;
                const char* b0b = smem + BS2_OFF + buf*4096 + hq*512;
                const char* b1b = b0b + 4*512;
#pragma unroll
                for (int k4 = 0; k4 < 16; k4++) {
                    float4 a4 = *(const float4*)(asb + k4*16);
                    ulonglong2 p00 = *(const ulonglong2*)(b0b + k4*32);
                    ulonglong2 p01 = *(const ulonglong2*)(b0b + k4*32 + 16);
                    ulonglong2 p10 = *(const ulonglong2*)(b1b + k4*32);
                    ulonglong2 p11 = *(const ulonglong2*)(b1b + k4*32 + 16);
                    acc0 = fma2(pack2(a4.x, a4.x), p00.x, acc0);
                    acc1 = fma2(pack2(a4.x, a4.x), p10.x, acc1);
                    acc0 = fma2(pack2(a4.y, a4.y), p00.y, acc0);
                    acc1 = fma2(pack2(a4.y, a4.y), p10.y, acc1);
                    acc0 = fma2(pack2(a4.z, a4.z), p01.x, acc0);
                    acc1 = fma2(pack2(a4.z, a4.z), p11.x, acc1);
                    acc0 = fma2(pack2(a4.w, a4.w), p01.y, acc0);
                    acc1 = fma2(pack2(a4.w, a4.w), p11.y, acc1);
                }
                __syncthreads();
            }
            // al @ PZ term (K=32)
#pragma unroll
            for (int s = 0; s < SS; s++) {
                float a = alsm[m*33 + s];
                ull w0 = __ldcg(pz0 + s*64);
                ull w1 = __ldcg(pz1 + s*64);
                ull p = pack2(a, a);
                acc0 = fma2(p, w0, acc0);
                acc1 = fma2(p, w1, acc1);
            }
        }
        {
            const int h = base + hq;
            float2 v0 = unpack2(acc0);   // (i, f)
            float2 v1 = unpack2(acc1);   // (g, o)
            const size_t zb = ((size_t)t*Z4H)*64 + m;
            float zi = v0.x + g_zx[zb + (size_t)h*64];
            float zf = v0.y + g_zx[zb + (size_t)(512 + h)*64];
            float zg = v1.x + g_zx[zb + (size_t)(1024 + h)*64];
            float zo = v1.y + g_zx[zb + (size_t)(1536 + h)*64];
            float ii = 1.f/(1.f + expf(-zi));
            float ff = 1.f/(1.f + expf(-zf));
            float oo = 1.f/(1.f + expf(-zo));
            float c2 = ff*g_cT[h*64 + m] + ii*tanhf(zg);
            float h2 = oo*tanhf(c2);
            g_cT[h*64 + m] = c2;
            __stcg(&g_h[nxt][m*HH + h], h2);
        }
        gbar();

        // ============ phase BE: q = h2@WqT, e = h2@WaT (paired weights) ======
        {
            float accq = 0.f, acce = 0.f;
            {
#pragma unroll
                for (int u = 0; u < 4; u++)
                    cpasync16(sb + AS_OFF + a_mm[u]*272 + a_kq[u]*16,
                              &g_h[nxt][(size_t)a_mm[u]*HH + a_kq[u]*4]);
                if (tid < 128)
                    cpasync16(sb + BQI_OFF + q_row*512 + b_c16*16,
                              g_WQAI + q_srcrow + b_c16*2);
                cp_commit();
            }
            for (int c = 0; c < 8; c++) {
                const int buf = c & 1;
                if (c + 1 < 8) {
                    const int kb = (c + 1) * 64;
                    const int nb = (c + 1) & 1;
#pragma unroll
                    for (int u = 0; u < 4; u++)
                        cpasync16(sb + AS_OFF + nb*17408 + a_mm[u]*272 + a_kq[u]*16,
                                  &g_h[nxt][(size_t)a_mm[u]*HH + kb + a_kq[u]*4]);
                    if (tid < 128)
                        cpasync16(sb + BQI_OFF + nb*2048 + q_row*512 + b_c16*16,
                                  g_WQAI + q_srcrow + kb + b_c16*2);
                    cp_commit();
                    cp_wait1();
                } else {
                    cp_wait0();
                }
                __syncthreads();
                const char* asb = smem + AS_OFF + buf*17408 + m*272;
                const char* qb  = smem + BQI_OFF + buf*2048 + hq*512;
#pragma unroll
                for (int k4 = 0; k4 < 16; k4++) {
                    float4 a4 = *(const float4*)(asb + k4*16);
                    ulonglong2 w0 = *(const ulonglong2*)(qb + k4*32);
                    ulonglong2 w1 = *(const ulonglong2*)(qb + k4*32 + 16);
                    float2 f0 = unpack2(w0.x), f1 = unpack2(w0.y);
                    float2 f2 = unpack2(w1.x), f3 = unpack2(w1.y);
                    accq += a4.x*f0.x; acce += a4.x*f0.y;
                    accq += a4.y*f1.x; acce += a4.y*f1.y;
                    accq += a4.z*f2.x; acce += a4.z*f2.y;
                    accq += a4.w*f3.x; acce += a4.w*f3.y;
                }
                __syncthreads();
            }
            __stcg(&g_q[m*HH + base + hq], accq);
            __stcg(&g_e[m*HH + base + hq], acce);
        }
        gbar();

        // ====== phase CD: scores + softmax + ctx + attn2 (blocks j<64) ======
        if (j < BB) {
            const int b = j;
            for (int i = tid; i < HH; i += 256) {
                qs[i] = __ldcg(&g_q[b*HH + i]);
                vs[i] = vvec[i];
            }
            __syncthreads();
            int w = tid >> 5, lane = tid & 31;
#pragma unroll
            for (int si = 0; si < 4; si++) {
                int s = (w << 2) + si;
                const float* kp = g_keys + (size_t)(b*SS + s)*HH;
                float acc = 0.f;
                for (int h = lane; h < HH; h += 32)
                    acc += tanh_a(kp[h] + qs[h]) * vs[h];
#pragma unroll
                for (int off = 16; off; off >>= 1)
                    acc += __shfl_down_sync(0xffffffffu, acc, off);
                if (lane == 0) sc2[s] = acc;
            }
            __syncthreads();
            if (tid < SS) {
                float x = sc2[tid];
                float mx = x;
#pragma unroll
                for (int off = 16; off; off >>= 1) mx = fmaxf(mx, __shfl_xor_sync(0xffffffffu, mx, off));
                float e = expf(x - mx);
                float sm = e;
#pragma unroll
                for (int off = 16; off; off >>= 1) sm += __shfl_xor_sync(0xffffffffu, sm, off);
                float av = e / sm;
                al2[tid] = av;
                __stcg(&g_al[b*SS + tid], av);
            }
            __syncthreads();
            {
                int n0 = tid * 2;
                float acc0c = 0.f, acc1c = 0.f;
#pragma unroll
                for (int s = 0; s < SS; s++) {
                    float2 pv = *(const float2*)&g_P[(size_t)(b*SS + s)*HH + n0];
                    acc0c += al2[s] * pv.x;
                    acc1c += al2[s] * pv.y;
                }
                float2 ev = __ldcg((const float2*)&g_e[b*HH + n0]);
                float v0 = ev.x + acc0c;
                float v1 = ev.y + acc1c;
                float2 av2; av2.x = v0; av2.y = v1;
                __stcg((float2*)&g_aprev[b*HH + n0], av2);   // used by old path (t<TSPLIT)
                __half h0b = __float2half(v0);
                __half h1b = __float2half(v1);
                size_t ar = ((size_t)(t*BB + b))*HH + n0;
                unsigned short h0u = *(unsigned short*)&h0b, h1u = *(unsigned short*)&h1b;
                __stcg((unsigned*)(g_Ah + ar), (unsigned)h0u | ((unsigned)h1u << 16));
            }
        }
        gbar();   // publishes g_gen = 3*(t+1)
    }
}

// ----------------------------- mma tile ----------------------------------------
__device__ void mma_tile(char* smem, int bm, int bn,
                         const float* __restrict__ bias, float* __restrict__ C) {
    const uint32_t sb = smem_u32(smem);
    const int tid = threadIdx.x;
    const int wid = tid >> 5, lane = tid & 31;
    const int warpM = wid >> 2, warpN = wid & 3;

    float acc[4][4][4];
#pragma unroll
    for (int i = 0; i < 4; i++)
#pragma unroll
        for (int jj = 0; jj < 4; jj++)
#pragma unroll
            for (int q = 0; q < 4; q++) acc[i][jj][q] = 0.f;

    auto load_stage = [&](int st, int kt) {
        uint32_t base = sb + st * STAGEB;
        const int k0 = kt * 32;
#pragma unroll
        for (int i = 0; i < 2; i++) {
            int c = tid + 256*i;
            int row = c >> 2, ch = c & 3;
            uint32_t so = (uint32_t)(row*ROWB + ch*16);
            size_t gA = (size_t)(bm + row)*HH + k0 + ch*8;
            size_t gB = (size_t)(bn + row)*HH + k0 + ch*8;
            cpasync16(base + 0*TILEB + so, g_Ah + gA);
            cpasync16(base + 1*TILEB + so, g_Bh + gB);
        }
        cp_commit();
    };

    load_stage(0, 0);

    const int jA = lane >> 3;
    const int rowA = (jA & 1)*8 + (lane & 7);
    const int colA = (jA >> 1)*16;
    const int rowB = lane & 7;
    const int colB = ((lane >> 3) & 1)*16;

    for (int kt = 0; kt < 16; kt++) {
        if (kt < 15) { load_stage((kt + 1) & 1, kt + 1); cp_wait1(); }
        else         { cp_wait0(); }
        __syncthreads();

        uint32_t base = sb + (kt & 1) * STAGEB;
        uint32_t sAh = base, sBh = base + TILEB;

#pragma unroll
        for (int ks = 0; ks < 2; ks++) {
            uint32_t bh[4][2];
#pragma unroll
            for (int nt = 0; nt < 4; nt++) {
                uint32_t off = (uint32_t)((warpN*32 + nt*8 + rowB)*ROWB + ks*32 + colB);
                ldsm2(bh[nt], sBh + off);
            }
#pragma unroll
            for (int mt = 0; mt < 4; mt++) {
                uint32_t ah[4];
                uint32_t off = (uint32_t)((warpM*64 + mt*16 + rowA)*ROWB + ks*32 + colA);
                ldsm4(ah, sAh + off);
#pragma unroll
                for (int nt = 0; nt < 4; nt++) {
                    mma16816(acc[mt][nt], ah, bh[nt]);
                }
            }
        }
        __syncthreads();
    }

    const int g = lane >> 2, tg = lane & 3;
#pragma unroll
    for (int mt = 0; mt < 4; mt++) {
        int row0 = bm + warpM*64 + mt*16 + g;
        int row1 = row0 + 8;
#pragma unroll
        for (int nt = 0; nt < 4; nt++) {
            int col = bn + warpN*32 + nt*8 + tg*2;
            if (col >= VV) continue;
            float2 bi = *(const float2*)(bias + col);
            if (row0 < BB*TT) {
                int tt = row0 >> 6, b = row0 & 63;
                float2 o; o.x = acc[mt][nt][0] + bi.x; o.y = acc[mt][nt][1] + bi.y;
                *(float2*)(C + ((size_t)(b*TT + tt))*VV + col) = o;
            }
            if (row1 < BB*TT) {
                int tt = row1 >> 6, b = row1 & 63;
                float2 o; o.x = acc[mt][nt][2] + bi.x; o.y = acc[mt][nt][3] + bi.y;
                *(float2*)(C + ((size_t)(b*TT + tt))*VV + col) = o;
            }
        }
    }
}

// ----------------------------- the single fused kernel -------------------------
__global__ void __launch_bounds__(256, 2) k_all(
        const void* __restrict__ dec,
        const float* __restrict__ memory,
        const float* __restrict__ h0,
        const float* __restrict__ c0,
        const float* __restrict__ emb,
        const float* __restrict__ Wk,
        const float* __restrict__ Wr,
        const float* __restrict__ bb,
        const float* __restrict__ Wq,
        const float* __restrict__ Wa,
        const float* __restrict__ Wm,
        const float* __restrict__ Wfc,
        const float* __restrict__ vvec,
        const float* __restrict__ bias,
        float* __restrict__ C) {
    extern __shared__ char smem[];
    __shared__ int s_idx;
    const int tid = threadIdx.x;
    PSmem* ps = (PSmem*)smem;
    GSmem* gs = (GSmem*)smem;
    WSmem* ws = (WSmem*)smem;

    // ---------------- queue 1: loop prerequisites (all blocks) ----------------
    for (;;) {
        if (tid == 0) s_idx = (int)atomicAdd(&g_ptile, 1u);
        __syncthreads();
        int i = s_idx;
        if (i >= P1TOTAL) break;
        if (i < PB_TW2)       p_init(i, tid, h0, c0);
        else if (i < PB_TWQ)  p_tw2(ps, i - PB_TW2, tid, Wk, Wr);
        else if (i < PB_ZX)   p_twq(ps, i - PB_TWQ, tid, Wq, Wa);
        else if (i < PB_KEY)  p_zx(gs, i - PB_ZX, tid, dec, emb, Wk, bb);
        else if (i < PB_P)    p_kp(gs, i - PB_KEY, tid, memory, Wm, g_keys);
        else                  p_kp(gs, i - PB_P, tid, memory, Wa + HH*HH, g_P);
        __syncthreads();
    }
    __syncthreads();
    if (tid == 0) {
        __threadfence();
        atom_add_ar(&g_pdone, 1u);
    }

    if (blockIdx.x < NBLK) {
        if (tid == 0) {
            while (ld_acq(&g_pdone) < GRID_FUSED) { }
        }
        __syncthreads();
        loop_path(smem, vvec);
    } else {
        // queue 2a: Wcomb + PZ (needed by loop at t >= TSPLIT)
        for (;;) {
            if (tid == 0) s_idx = (int)atomicAdd(&g_ptile2, 1u);
            __syncthreads();
            int i = s_idx;
            if (i >= Q2A_TOTAL) break;
            if (i < NT_WCOMB) p_wcomb(ws, i, tid, Wa, Wk, Wr);
            else              p_pz(ws, i - NT_WCOMB, tid, Wk);
            __syncthreads();
        }
        __syncthreads();
        if (tid == 0) {
            __threadfence();
            atom_add_ar(&g_zdone, 1u);
        }
        // queue 2b: cvtB (needed by mma pool only)
        for (;;) {
            if (tid == 0) s_idx = (int)atomicAdd(&g_ptile3, 1u);
            __syncthreads();
            int i = s_idx;
            if (i >= NT_CVTB) break;
            p_cvtB(ps, i, tid, Wfc);
            __syncthreads();
        }
        __syncthreads();
        if (tid == 0) {
            __threadfence();
            atom_add_ar(&g_cdone, 1u);
        }
    }

    // ---------------- mma worker pool (all blocks; gated on cvtB done) -------
    if (tid == 0) {
        while (ld_acq(&g_cdone) < NWORK)
            asm volatile("nanosleep.u32 256;");
    }
    __syncthreads();

    for (;;) {
        if (tid == 0) s_idx = (int)atomicAdd(&g_tile, 1u);
        __syncthreads();
        int idx = s_idx;
        if (idx >= NTILES) break;
        int by = idx / NXB, bx = idx - by*NXB;
        if (tid == 0) {
            int tmaxv = 2*by + 1; if (tmaxv > TT-1) tmaxv = TT-1;
            unsigned need = 3u * (unsigned)(tmaxv + 1);
            while (ld_rlx(&g_gen2) < need)
                asm volatile("nanosleep.u32 1024;");
            (void)ld_acq(&g_gen2);
        }
        __syncthreads();
        mma_tile(smem, by*128, bx*128, bias, C);
        __syncthreads();
    }
}

// ----------------------------- launch sequence --------------------------------
extern "C" void kernel_launch(void* const* d_in, const int* in_sizes, int n_in,
                              void* d_out, int out_size) {
    const void*  dec    = d_in[0];
    const float* memory = (const float*)d_in[1];
    const float* h0     = (const float*)d_in[2];
    const float* c0     = (const float*)d_in[3];
    const float* emb    = (const float*)d_in[4];
    const float* Wk     = (const float*)d_in[5];
    const float* Wr     = (const float*)d_in[6];
    const float* bb     = (const float*)d_in[7];
    const float* Wm     = (const float*)d_in[8];
    const float* Wq     = (const float*)d_in[9];
    const float* vv     = (const float*)d_in[10];
    const float* Wa     = (const float*)d_in[11];
    const float* Wfc    = (const float*)d_in[12];
    const float* bfc    = (const float*)d_in[13];
    float* out = (float*)d_out;

    cudaFuncSetAttribute(k_all, cudaFuncAttributeMaxDynamicSharedMemorySize, SMEM_FUSED);

    k_rst<<<1, 32>>>();
    k_all<<<GRID_FUSED, 256, SMEM_FUSED>>>(dec, memory, h0, c0, emb, Wk, Wr, bb,
                                           Wq, Wa, Wm, Wfc, vv, bfc, out);
}